// round 17
// baseline (speedup 1.0000x reference)
#include <cuda_runtime.h>
#include <cuda_fp16.h>
#include <cstdint>
#include <math.h>

// ============================================================================
// Equiformer FFN via mma.sync m16n8k16 fp16 (A fp16, B fp16, fp32 acc).
// CTA = 64 nodes, 256 threads (8 warps 2m x 4n), 2 CTAs/SM (88.6KB smem).
// R17: P0 true double-buffered B; P2 merged to one phase per component with
// W1_1/W2_1 RESIDENT across all 3 components. P3 weights resident (as R16).
// ============================================================================

#define THREADS 256
#define MAXCTA  1563

// ---- pre-converted weights (fp16) ----
#define OFF10 0        // [672 n][136]   (7 chunks of 96 n, 13056 each)
#define OFF11 91392    // [192 n][72]
#define OFF12 105216   // [96 n][40]
#define OFF20 109056   // 8 x [128 n][56]   (K chunks of 48)
#define OFF21 166400   // [64 n][200]
#define OFF22 179200   // [32 n][104]
#define WTOT  182528
__device__ __align__(16) uint16_t g_wh[WTOT];

// ---- pre-converted X (fp16) per 64-node CTA ----
#define XBLK 35328
__device__ __align__(16) uint16_t g_x[(size_t)MAXCTA * XBLK];

// scalars fp16 [64 r][392] + gates fp32 [64 r][288]
__device__ __align__(16) uint16_t g_sc[(size_t)MAXCTA * 25088];
__device__ __align__(16) float    g_gate[(size_t)MAXCTA * 18432];

#define SM_TOT 88576

__device__ __forceinline__ uint32_t s2u(const void* p) {
    uint32_t a;
    asm("{ .reg .u64 t; cvta.to.shared.u64 t, %1; cvt.u32.u64 %0, t; }" : "=r"(a) : "l"(p));
    return a;
}
__device__ __forceinline__ void ldm_x4(uint32_t d[4], uint32_t a) {
    asm volatile("ldmatrix.sync.aligned.m8n8.x4.shared.b16 {%0,%1,%2,%3}, [%4];"
                 : "=r"(d[0]), "=r"(d[1]), "=r"(d[2]), "=r"(d[3]) : "r"(a));
}
__device__ __forceinline__ void ldm_x2(uint32_t d[2], uint32_t a) {
    asm volatile("ldmatrix.sync.aligned.m8n8.x2.shared.b16 {%0,%1}, [%2];"
                 : "=r"(d[0]), "=r"(d[1]) : "r"(a));
}
__device__ __forceinline__ void mma_f16(float (&c)[4], const uint32_t (&a)[4],
                                        const uint32_t (&b)[2]) {
    asm volatile("mma.sync.aligned.m16n8k16.row.col.f32.f16.f16.f32 "
                 "{%0,%1,%2,%3},{%4,%5,%6,%7},{%8,%9},{%0,%1,%2,%3};"
                 : "+f"(c[0]), "+f"(c[1]), "+f"(c[2]), "+f"(c[3])
                 : "r"(a[0]), "r"(a[1]), "r"(a[2]), "r"(a[3]), "r"(b[0]), "r"(b[1]));
}
__device__ __forceinline__ uint32_t pk16(float v0, float v1) {
    return (uint32_t)__half_as_ushort(__float2half_rn(v0)) |
           ((uint32_t)__half_as_ushort(__float2half_rn(v1)) << 16);
}
__device__ __forceinline__ void cp16(uint32_t dst, const void* src) {
    asm volatile("cp.async.cg.shared.global [%0], [%1], 16;" :: "r"(dst), "l"(src));
}
#define CP_COMMIT() asm volatile("cp.async.commit_group;" ::: "memory")
#define CP_WAIT0()  asm volatile("cp.async.wait_group 0;" ::: "memory")
#define CP_WAIT1()  asm volatile("cp.async.wait_group 1;" ::: "memory")

__device__ __forceinline__ void cpy1(uint32_t d, const uint16_t* s, int elems) {
    const int n16 = elems >> 3;
    for (int i = threadIdx.x; i < n16; i += THREADS) cp16(d + i * 16, s + i * 8);
}
// scalars: 64 rows x 6 chunks of 16B from [r][392] col kcOff -> [r][56pad]
__device__ __forceinline__ void cpy_sc48(uint32_t d, const uint16_t* s, int kcOff) {
    for (int i = threadIdx.x; i < 384; i += THREADS) {
        const int r = i / 6, ch = i - r * 6;
        cp16(d + r * 112 + ch * 16, s + r * 392 + kcOff + ch * 8);
    }
}

template <int NTW>
__device__ __forceinline__ void zacc(float (&acc)[2][NTW][4]) {
#pragma unroll
    for (int m = 0; m < 2; m++)
#pragma unroll
        for (int j = 0; j < NTW; j++)
#pragma unroll
            for (int q = 0; q < 4; q++) acc[m][j][q] = 0.0f;
}

template <int KT, int NTW>
__device__ __forceinline__ void mma1(uint32_t uA, uint32_t uB, int Kpad,
                                     int rowBase, int n8Base, int lane,
                                     float (&acc)[2][NTW][4]) {
    const int ar  = rowBase + (lane & 15);
    const int ak8 = (lane >> 4) * 8;
    const int bn  = lane & 7;
    const int bk8 = ((lane >> 3) & 1) * 8;
#pragma unroll 1
    for (int kt = 0; kt < KT; kt++) {
        const int kb = kt * 16;
        uint32_t A[2][4];
#pragma unroll
        for (int m = 0; m < 2; m++)
            ldm_x4(A[m], uA + (uint32_t)(((ar + m * 16) * Kpad + kb + ak8) * 2));
#pragma unroll
        for (int j = 0; j < NTW; j++) {
            uint32_t B[2];
            ldm_x2(B, uB + (uint32_t)((((n8Base + j) * 8 + bn) * Kpad + kb + bk8) * 2));
#pragma unroll
            for (int m = 0; m < 2; m++) mma_f16(acc[m][j], A[m], B);
        }
    }
}

// ---- prep1: weights -> fp16 ----
__device__ __forceinline__ void prep_w(const float* __restrict__ W, int K, int N,
                                       int Kpad, int base) {
    const int tot = K * N;
    for (int idx = blockIdx.x * blockDim.x + threadIdx.x; idx < tot;
         idx += gridDim.x * blockDim.x) {
        const int k = idx / N, n = idx - k * N;
        g_wh[base + n * Kpad + k] =
            __half_as_ushort(__float2half_rn(__ldg(&W[idx])));
    }
}
__global__ void prep1(const float* W1_0, const float* W1_1, const float* W1_2,
                      const float* W2_0, const float* W2_1, const float* W2_2) {
    prep_w(W1_0, 128, 672, 136, OFF10);
    prep_w(W1_1, 64, 192, 72, OFF11);
    prep_w(W1_2, 32, 96, 40, OFF12);
    for (int idx = blockIdx.x * blockDim.x + threadIdx.x; idx < 384 * 128;
         idx += gridDim.x * blockDim.x) {
        const int k = idx / 128, n = idx - k * 128;
        const int kc = k / 48, kk = k - kc * 48;
        g_wh[OFF20 + kc * 7168 + n * 56 + kk] =
            __half_as_ushort(__float2half_rn(__ldg(&W2_0[idx])));
    }
    prep_w(W2_1, 192, 64, 200, OFF21);
    prep_w(W2_2, 96, 32, 104, OFF22);
}

// ---- prep2: X -> fp16, vectorized 16B stores ----
__global__ void prep2(const float* __restrict__ X, int Nn, int nct) {
    const int total = nct * 64 * 60;
    for (int idx = blockIdx.x * blockDim.x + threadIdx.x; idx < total;
         idx += gridDim.x * blockDim.x) {
        const int node = idx / 60, u = idx - node * 60;
        const int r = node & 63, cta = node >> 6;
        const float* p = X + (size_t)min(node, Nn - 1) * 480;
        const size_t base = (size_t)cta * XBLK;
        float v[8];
        size_t off;
        if (u < 16) {
#pragma unroll
            for (int q = 0; q < 8; q++) v[q] = __ldg(&p[u * 8 + q]);
            off = base + r * 136 + u * 8;
        } else if (u < 40) {
            const int i = (u - 16) >> 3, b = (u - 16) & 7;
#pragma unroll
            for (int q = 0; q < 8; q++) v[q] = __ldg(&p[128 + 24 * b + i + 3 * q]);
            off = base + 8704 + i * 4608 + r * 72 + b * 8;
        } else {
            const int i = (u - 40) >> 2, b = (u - 40) & 3;
#pragma unroll
            for (int q = 0; q < 8; q++) v[q] = __ldg(&p[320 + 40 * b + i + 5 * q]);
            off = base + 22528 + i * 2560 + r * 40 + b * 8;
        }
        uint4 o;
        o.x = pk16(v[0], v[1]);
        o.y = pk16(v[2], v[3]);
        o.z = pk16(v[4], v[5]);
        o.w = pk16(v[6], v[7]);
        *reinterpret_cast<uint4*>(g_x + off) = o;
    }
}

__global__ void __launch_bounds__(THREADS, 2)
ffn_main(const float* __restrict__ attr, const float* __restrict__ b1,
         const float* __restrict__ b2, float* __restrict__ out, int Nn) {
    extern __shared__ char smem[];
    float* sAttr = (float*)smem;
    const uint32_t sb = s2u(smem);
    const int tid = threadIdx.x, lane = tid & 31, w = tid >> 5;
    const int g = lane >> 2, t2 = lane & 3;
    const int mt = w >> 2, nt = w & 3;   // 2m x 4n
    const size_t cta = blockIdx.x;
    const int nbase = (int)cta * 64;
    const uint16_t* x = g_x + cta * XBLK;
    uint16_t* sc = g_sc + cta * 25088;
    float* gate = g_gate + cta * 18432;

    const float I10 = 0.08838834764831843f, I11 = 0.125f, I12 = 0.17677669529663687f;
    const float I20 = 0.05103103630798288f, I21 = 0.07216878364870323f,
                I22 = 0.10206207261596577f;

    // ===== P0: h0 = x0 @ W1_0 (7 N-chunks of 96, double-buffered B) =====
    // A seg0 @512 (17408B); B bufs @17920 / @44032 (26112B each)
    cpy1(sb + 512, x, 8704);
    cpy1(sb + 17920, g_wh + OFF10, 13056);
    CP_COMMIT();
    if (tid < 64) sAttr[tid] = attr[min(nbase + tid, Nn - 1)];
    {
        const uint32_t bB[2] = {sb + 17920, sb + 44032};
        for (int ch = 0; ch < 7; ch++) {
            const int s = ch & 1;
            if (ch < 6) {
                cpy1(bB[1 - s], g_wh + OFF10 + (ch + 1) * 13056, 13056);
                CP_COMMIT();
                CP_WAIT1();
            } else {
                CP_WAIT0();
            }
            __syncthreads();
            float acc[2][3][4];
            zacc<3>(acc);
            mma1<8, 3>(sb + 512, bB[s], 136, mt * 32, nt * 3, lane, acc);
            __syncthreads();
            if (ch == 6) {
                // prefetch P1 kc0: A scalars 0..47 @512, B W2_0 kc0 @14848
                cpy_sc48(sb + 512, sc, 0);
                cpy1(sb + 14848, g_wh + OFF20, 7168);
                CP_COMMIT();
            }
#pragma unroll
            for (int m = 0; m < 2; m++) {
                const int r0 = mt * 32 + m * 16 + g;
#pragma unroll
                for (int j = 0; j < 3; j++) {
                    const int gc = ch * 96 + (nt * 3 + j) * 8 + t2 * 2;
                    const float bb0 = __ldg(&b1[gc]), bb1 = __ldg(&b1[gc + 1]);
#pragma unroll
                    for (int h2 = 0; h2 < 2; h2++) {
                        const int r = r0 + h2 * 8;
                        const float a = sAttr[r] * I10;
                        const float x0 = acc[m][j][h2 * 2] * a + bb0;
                        const float x1 = acc[m][j][h2 * 2 + 1] * a + bb1;
                        const float s0 = 1.0f / (1.0f + __expf(-x0));
                        const float s1 = 1.0f / (1.0f + __expf(-x1));
                        if (gc < 384)
                            *reinterpret_cast<uint32_t*>(sc + r * 392 + gc) =
                                pk16(x0 * s0, x1 * s1);
                        else
                            *reinterpret_cast<float2*>(gate + r * 288 + gc - 384) =
                                make_float2(s0, s1);
                    }
                }
            }
        }
    }

    // ===== P1: out0 = scalars @ W2_0 (8 K-chunks of 48, double-buffered) =====
    // A [64][56] @512/@7680; B [128][56] @14848/@29184
    {
        const uint32_t aB[2] = {sb + 512, sb + 7680};
        const uint32_t bB[2] = {sb + 14848, sb + 29184};
        float acc[2][4][4];
        zacc<4>(acc);
        for (int kc = 0; kc < 8; kc++) {
            const int s = kc & 1;
            if (kc < 7) {
                cpy_sc48(aB[1 - s], sc, (kc + 1) * 48);
                cpy1(bB[1 - s], g_wh + OFF20 + (kc + 1) * 7168, 7168);
                CP_COMMIT();
                CP_WAIT1();
            } else {
                CP_WAIT0();
            }
            __syncthreads();
            mma1<3, 4>(aB[s], bB[s], 56, mt * 32, nt * 4, lane, acc);
            __syncthreads();
        }
        // prefetch P2 residents + X1_0: X1 @512, W1_1 @9728, W2_1 @62976
        cpy1(sb + 512, x + 8704, 4608);
        cpy1(sb + 9728, g_wh + OFF11, 13824);
        cpy1(sb + 62976, g_wh + OFF21, 12800);
        CP_COMMIT();
        // out0 epilogue
#pragma unroll
        for (int m = 0; m < 2; m++) {
            const int r0 = mt * 32 + m * 16 + g;
#pragma unroll
            for (int j = 0; j < 4; j++) {
                const int c = (nt * 4 + j) * 8 + t2 * 2;
                const float bb0 = __ldg(&b2[c]), bb1 = __ldg(&b2[c + 1]);
#pragma unroll
                for (int h2 = 0; h2 < 2; h2++) {
                    const int r = r0 + h2 * 8, node = nbase + r;
                    if (node < Nn) {
                        const float a = sAttr[r] * I20;
                        *reinterpret_cast<float2*>(out + (size_t)node * 480 + c) =
                            make_float2(acc[m][j][h2 * 2] * a + bb0,
                                        acc[m][j][h2 * 2 + 1] * a + bb1);
                    }
                }
            }
        }
    }

    // ===== P2: mid1_i -> out1_i, W1_1/W2_1 resident (i=0..2) =====
    // X1 @512 (9216B); W1_1 @9728 (27648B); mid @37376 [64][200] (25600B);
    // W2_1 @62976 [64][200] (25600B)
    {
        uint16_t* mB = (uint16_t*)(smem + 37376);
        for (int i = 0; i < 3; i++) {
            CP_WAIT0();
            __syncthreads();
            // mid mma: N=192, K=64
            float acc[2][6][4];
            zacc<6>(acc);
            mma1<4, 6>(sb + 512, sb + 9728, 72, mt * 32, nt * 6, lane, acc);
            __syncthreads();
            if (i < 2) {
                cpy1(sb + 512, x + 8704 + (i + 1) * 4608, 4608);
                CP_COMMIT();
            } else {
                // P3 preload (X1/W1_1 low regions dead): X2_0 @512, W1_2 @5632,
                // W2_2 @13312
                cpy1(sb + 512, x + 22528, 2560);
                cpy1(sb + 5632, g_wh + OFF12, 3840);
                cpy1(sb + 13312, g_wh + OFF22, 3328);
                CP_COMMIT();
            }
            // mid epilogue -> smem fp16 [r][200]
#pragma unroll
            for (int m = 0; m < 2; m++) {
                const int r0 = mt * 32 + m * 16 + g;
#pragma unroll
                for (int j = 0; j < 6; j++) {
                    const int c = (nt * 6 + j) * 8 + t2 * 2;
#pragma unroll
                    for (int h2 = 0; h2 < 2; h2++) {
                        const int r = r0 + h2 * 8;
                        const float a = sAttr[r] * I11;
                        const float2 gg =
                            *reinterpret_cast<const float2*>(gate + r * 288 + c);
                        *reinterpret_cast<uint32_t*>(mB + r * 200 + c) =
                            pk16(acc[m][j][h2 * 2] * a * gg.x,
                                 acc[m][j][h2 * 2 + 1] * a * gg.y);
                    }
                }
            }
            __syncthreads();
            // out1 mma: K=192
            float acc2[2][2][4];
            zacc<2>(acc2);
            mma1<12, 2>(sb + 37376, sb + 62976, 200, mt * 32, nt * 2, lane, acc2);
#pragma unroll
            for (int m = 0; m < 2; m++) {
                const int r0 = mt * 32 + m * 16 + g;
#pragma unroll
                for (int j = 0; j < 2; j++) {
                    const int c = (nt * 2 + j) * 8 + t2 * 2;
#pragma unroll
                    for (int h2 = 0; h2 < 2; h2++) {
                        const int r = r0 + h2 * 8, node = nbase + r;
                        if (node < Nn) {
                            const float a = sAttr[r] * I21;
                            out[(size_t)node * 480 + 128 + c * 3 + i] =
                                acc2[m][j][h2 * 2] * a;
                            out[(size_t)node * 480 + 128 + (c + 1) * 3 + i] =
                                acc2[m][j][h2 * 2 + 1] * a;
                        }
                    }
                }
            }
        }
    }

    // ===== P3: mid2_i -> out2_i, W1_2/W2_2 resident (i=0..4) =====
    // X2 @512 (5120B); W1_2 @5632 (7680B); W2_2 @13312 (6656B); mid @19968
    {
        uint16_t* mB = (uint16_t*)(smem + 19968);
        for (int i = 0; i < 5; i++) {
            CP_WAIT0();
            __syncthreads();
            float acc[2][3][4];
            zacc<3>(acc);
            mma1<2, 3>(sb + 512, sb + 5632, 40, mt * 32, nt * 3, lane, acc);
            __syncthreads();
            if (i < 4) {
                cpy1(sb + 512, x + 22528 + (i + 1) * 2560, 2560);
                CP_COMMIT();
            }
#pragma unroll
            for (int m = 0; m < 2; m++) {
                const int r0 = mt * 32 + m * 16 + g;
#pragma unroll
                for (int j = 0; j < 3; j++) {
                    const int c = (nt * 3 + j) * 8 + t2 * 2;
#pragma unroll
                    for (int h2 = 0; h2 < 2; h2++) {
                        const int r = r0 + h2 * 8;
                        const float a = sAttr[r] * I12;
                        const float2 gg = *reinterpret_cast<const float2*>(
                            gate + r * 288 + 192 + c);
                        *reinterpret_cast<uint32_t*>(mB + r * 104 + c) =
                            pk16(acc[m][j][h2 * 2] * a * gg.x,
                                 acc[m][j][h2 * 2 + 1] * a * gg.y);
                    }
                }
            }
            __syncthreads();
            float acc2[2][1][4];
            zacc<1>(acc2);
            mma1<6, 1>(sb + 19968, sb + 13312, 104, mt * 32, nt, lane, acc2);
            __syncthreads();
#pragma unroll
            for (int m = 0; m < 2; m++) {
                const int r0 = mt * 32 + m * 16 + g;
                const int c = nt * 8 + t2 * 2;
#pragma unroll
                for (int h2 = 0; h2 < 2; h2++) {
                    const int r = r0 + h2 * 8, node = nbase + r;
                    if (node < Nn) {
                        const float a = sAttr[r] * I22;
                        out[(size_t)node * 480 + 320 + c * 5 + i] =
                            acc2[m][0][h2 * 2] * a;
                        out[(size_t)node * 480 + 320 + (c + 1) * 5 + i] =
                            acc2[m][0][h2 * 2 + 1] * a;
                    }
                }
            }
        }
    }
}

extern "C" void kernel_launch(void* const* d_in, const int* in_sizes, int n_in,
                              void* d_out, int out_size) {
    const float* X    = (const float*)d_in[0];
    const float* attr = (const float*)d_in[1];
    const float* W1_0 = (const float*)d_in[2];
    const float* W1_1 = (const float*)d_in[3];
    const float* W1_2 = (const float*)d_in[4];
    const float* b1   = (const float*)d_in[5];
    const float* W2_0 = (const float*)d_in[6];
    const float* W2_1 = (const float*)d_in[7];
    const float* W2_2 = (const float*)d_in[8];
    const float* b2   = (const float*)d_in[9];
    float* out = (float*)d_out;

    const int N = in_sizes[0] / 480;
    int nct = (N + 63) / 64;
    if (nct > MAXCTA) nct = MAXCTA;

    prep1<<<160, 256>>>(W1_0, W1_1, W1_2, W2_0, W2_1, W2_2);
    prep2<<<2048, 256>>>(X, N, nct);
    cudaFuncSetAttribute(ffn_main, cudaFuncAttributeMaxDynamicSharedMemorySize, SM_TOT);
    ffn_main<<<nct, THREADS, SM_TOT>>>(attr, b1, b2, out, N);
}